// round 16
// baseline (speedup 1.0000x reference)
#include <cuda_runtime.h>
#include <cuda_bf16.h>
#include <math.h>

// Problem constants
#define B_    4
#define S_    2048
#define D_    1024
#define H_    16
#define DH_   64
#define F_    4096
#define NTOK  (B_ * S_)        // 8192 tokens
#define NQKV  (3 * D_)         // 3072 fused qkv columns

// ---------------------------------------------------------------------------
// Scratch (static device globals — no runtime allocation allowed)
// ---------------------------------------------------------------------------
static __device__ __align__(256) __nv_bfloat16 g_x_h [(size_t)NTOK * D_];
static __device__ __align__(256) __nv_bfloat16 g_qkv [(size_t)NTOK * NQKV];
static __device__ __align__(256) __nv_bfloat16 g_attn[(size_t)NTOK * D_];
static __device__ float g_tmp [(size_t)NTOK * D_];    // residual sums pre-LN
static __device__ float g_y   [(size_t)NTOK * D_];    // LN1 output (exact f32)
static __device__ __align__(256) float g_ytf[(size_t)NTOK * D_];  // tf32 copy
static __device__ __align__(256) float g_ff [(size_t)NTOK * F_];  // FFN hidden (tf32)
static __device__ float g_bqkv[NQKV];                 // packed qkv bias

// bf16 weights for QKV/WO; tf32-rounded transposed weights for FFN
static __device__ __align__(256) __nv_bfloat16 g_wqkv_h[(size_t)D_ * NQKV];
static __device__ __align__(256) __nv_bfloat16 g_wo_h[(size_t)D_ * D_];
static __device__ __align__(256) float g_w1t[(size_t)F_ * D_];   // [F][D]
static __device__ __align__(256) float g_w2t[(size_t)D_ * F_];   // [D][F]

// ---------------------------------------------------------------------------
// PTX helpers
// ---------------------------------------------------------------------------
static __device__ __forceinline__ unsigned sptr(const void* p) {
    return (unsigned)__cvta_generic_to_shared(p);
}
static __device__ __forceinline__ void ldsm4(unsigned* r, unsigned addr) {
    asm volatile("ldmatrix.sync.aligned.m8n8.x4.shared.b16 {%0,%1,%2,%3}, [%4];"
                 : "=r"(r[0]), "=r"(r[1]), "=r"(r[2]), "=r"(r[3]) : "r"(addr));
}
static __device__ __forceinline__ void ldsm4t(unsigned* r, unsigned addr) {
    asm volatile("ldmatrix.sync.aligned.m8n8.x4.trans.shared.b16 {%0,%1,%2,%3}, [%4];"
                 : "=r"(r[0]), "=r"(r[1]), "=r"(r[2]), "=r"(r[3]) : "r"(addr));
}
static __device__ __forceinline__ void mma_bf16(float* c, const unsigned* a,
                                                unsigned b0, unsigned b1) {
    asm volatile(
        "mma.sync.aligned.m16n8k16.row.col.f32.bf16.bf16.f32 "
        "{%0,%1,%2,%3}, {%4,%5,%6,%7}, {%8,%9}, {%0,%1,%2,%3};"
        : "+f"(c[0]), "+f"(c[1]), "+f"(c[2]), "+f"(c[3])
        : "r"(a[0]), "r"(a[1]), "r"(a[2]), "r"(a[3]), "r"(b0), "r"(b1));
}
static __device__ __forceinline__ void mma_tf32(float* c, const unsigned* a,
                                                unsigned b0, unsigned b1) {
    asm volatile(
        "mma.sync.aligned.m16n8k8.row.col.f32.tf32.tf32.f32 "
        "{%0,%1,%2,%3}, {%4,%5,%6,%7}, {%8,%9}, {%0,%1,%2,%3};"
        : "+f"(c[0]), "+f"(c[1]), "+f"(c[2]), "+f"(c[3])
        : "r"(a[0]), "r"(a[1]), "r"(a[2]), "r"(a[3]), "r"(b0), "r"(b1));
}
static __device__ __forceinline__ float to_tf32(float x) {
    unsigned u;
    asm("cvt.rna.tf32.f32 %0, %1;" : "=r"(u) : "f"(x));
    return __uint_as_float(u);
}
// Fast exp for softmax weights (Schraudolph), 1/8 scale folded in.
static __device__ __forceinline__ float fexp8(float s) {
    return __int_as_float(__float2int_rn(fmaf(s, 1512775.395f, 1064986823.0f)));
}
#define CP_ASYNC16(dst, src) \
    asm volatile("cp.async.cg.shared.global [%0], [%1], 16;" :: "r"(dst), "l"(src))
#define CP_COMMIT() asm volatile("cp.async.commit_group;")
#define CP_WAITN(N) asm volatile("cp.async.wait_group %0;" :: "n"(N))

static __device__ __forceinline__ unsigned bf2u(__nv_bfloat162 v) {
    return *reinterpret_cast<unsigned*>(&v);
}

// ---------------------------------------------------------------------------
// Prep kernels
// ---------------------------------------------------------------------------
__global__ void tobf16_v4(const float* __restrict__ w,
                          __nv_bfloat16* __restrict__ oh, size_t n4)
{
    size_t i = (size_t)blockIdx.x * 256 + threadIdx.x;
    if (i >= n4) return;
    float4 v = ((const float4*)w)[i];
    __nv_bfloat162 a = __floats2bfloat162_rn(v.x, v.y);
    __nv_bfloat162 b = __floats2bfloat162_rn(v.z, v.w);
    ((uint2*)oh)[i] = make_uint2(bf2u(a), bf2u(b));
}

// wq/wk/wv [H,D,DH] -> [K=1024, N=3072] row-major bf16 (vectorized x4)
__global__ void pack_qkv_w4(const float* __restrict__ wq,
                            const float* __restrict__ wk,
                            const float* __restrict__ wv,
                            __nv_bfloat16* __restrict__ oh)
{
    size_t i = (size_t)blockIdx.x * 256 + threadIdx.x;
    if (i >= (size_t)D_ * NQKV / 4) return;
    size_t idx = i * 4;
    int d  = (int)(idx / NQKV);
    int j  = (int)(idx % NQKV);
    int p  = j / D_;
    int he = j % D_;
    int h  = he >> 6;
    int e  = he & 63;
    const float* w = (p == 0) ? wq : ((p == 1) ? wk : wv);
    float4 v = *(const float4*)&w[(size_t)h * D_ * DH_ + (size_t)d * DH_ + e];
    __nv_bfloat162 a = __floats2bfloat162_rn(v.x, v.y);
    __nv_bfloat162 b = __floats2bfloat162_rn(v.z, v.w);
    *(uint2*)&oh[idx] = make_uint2(bf2u(a), bf2u(b));
}

__global__ void pack_qkv_b(const float* __restrict__ bq,
                           const float* __restrict__ bk,
                           const float* __restrict__ bv,
                           float* __restrict__ out)
{
    int j = blockIdx.x * 256 + threadIdx.x;
    if (j >= NQKV) return;
    int p  = j / D_;
    int he = j % D_;
    const float* b = (p == 0) ? bq : ((p == 1) ? bk : bv);
    out[j] = b[he];
}

// src [K][N] f32 -> dst [N][K] f32, tf32-rounded (tiled transpose)
__global__ void transpose_tf32(const float* __restrict__ src,
                               float* __restrict__ dst, int K, int N)
{
    __shared__ float t[32][33];
    const int n0 = blockIdx.x * 32;
    const int k0 = blockIdx.y * 32;
    const int tx = threadIdx.x, ty = threadIdx.y;
#pragma unroll
    for (int i = 0; i < 4; i++)
        t[ty + 8 * i][tx] = src[(size_t)(k0 + ty + 8 * i) * N + n0 + tx];
    __syncthreads();
#pragma unroll
    for (int i = 0; i < 4; i++)
        dst[(size_t)(n0 + ty + 8 * i) * K + k0 + tx] = to_tf32(t[tx][ty + 8 * i]);
}

// ---------------------------------------------------------------------------
// bf16 1-MMA GEMM (QKV / WO). occ2, GS=3, prefetch issued before compute.
// ---------------------------------------------------------------------------
#define PA2   40
#define PB2   136
#define A_T   (128 * PA2)
#define B_T   (32 * PB2)
#define SMEM_1 (3 * (A_T + B_T) * 2)       // 56832 B

template <int OUTMODE>
__global__ __launch_bounds__(256, 2)
void mma_gemm_b16(const __nv_bfloat16* __restrict__ Ah,
                  const __nv_bfloat16* __restrict__ Bh,
                  const float* __restrict__ bias,
                  const float* __restrict__ resid,
                  float* __restrict__ C,
                  __nv_bfloat16* __restrict__ Ch,
                  int M, int N, int K)
{
    extern __shared__ __nv_bfloat16 dsm[];
    constexpr int STG = A_T + B_T;

    const int tid  = threadIdx.x;
    const int lane = tid & 31;
    const int warp = tid >> 5;
    const int wm   = warp >> 1;
    const int wn   = warp & 1;
    const int g    = lane >> 2;
    const int tg   = lane & 3;
    const int m0   = blockIdx.y * 128;
    const int n0   = blockIdx.x * 128;

    float acc[2][8][4];
#pragma unroll
    for (int i = 0; i < 2; i++)
#pragma unroll
        for (int j = 0; j < 8; j++)
#pragma unroll
            for (int q = 0; q < 4; q++) acc[i][j][q] = 0.f;

    const int T = K >> 5;

#define GLB(T_, S_)                                                            \
    {                                                                          \
        const int k0_ = (T_) * 32;                                             \
        __nv_bfloat16* sb_ = dsm + (S_) * STG;                                 \
        _Pragma("unroll")                                                      \
        for (int j = 0; j < 4; j++) {                                          \
            int c = tid + 256 * j;                                             \
            if (c < 512) {                                                     \
                int row = c >> 2, ch = c & 3;                                  \
                __nv_bfloat16* d = sb_ + row * PA2 + ch * 8;                   \
                const __nv_bfloat16* s =                                       \
                    Ah + (size_t)(m0 + row) * K + k0_ + ch * 8;                \
                CP_ASYNC16(sptr(d), s);                                        \
            } else {                                                           \
                int c2 = c - 512;                                              \
                int row = c2 >> 4, ch = c2 & 15;                               \
                __nv_bfloat16* d = sb_ + A_T + row * PB2 + ch * 8;             \
                const __nv_bfloat16* s =                                       \
                    Bh + (size_t)(k0_ + row) * N + n0 + ch * 8;                \
                CP_ASYNC16(sptr(d), s);                                        \
            }                                                                  \
        }                                                                      \
    }

    GLB(0, 0); CP_COMMIT();
    GLB(1, 1); CP_COMMIT();

    const int a_r  = wm * 32 + (lane & 15);
    const int a_kc = (lane >> 4) * 8;
    const int b_k  = (lane & 15);
    const int b_nc = wn * 64 + (lane >> 4) * 8;

    for (int t = 0; t < T; t++) {
        CP_WAITN(1);
        __syncthreads();
        if (t + 2 < T) { GLB(t + 2, (t + 2) % 3); CP_COMMIT(); }

        __nv_bfloat16* sAh = dsm + (t % 3) * STG;
        __nv_bfloat16* sBh = sAh + A_T;

#pragma unroll
        for (int kk = 0; kk < 32; kk += 16) {
            unsigned ah[2][4], bh[4][4];
#pragma unroll
            for (int mt = 0; mt < 2; mt++)
                ldsm4(ah[mt], sptr(sAh + (a_r + mt * 16) * PA2 + kk + a_kc));
#pragma unroll
            for (int np = 0; np < 4; np++)
                ldsm4t(bh[np], sptr(sBh + (kk + b_k) * PB2 + b_nc + np * 16));
#pragma unroll
            for (int mt = 0; mt < 2; mt++)
#pragma unroll
                for (int np = 0; np < 4; np++) {
                    mma_bf16(acc[mt][2 * np],     ah[mt], bh[np][0], bh[np][1]);
                    mma_bf16(acc[mt][2 * np + 1], ah[mt], bh[np][2], bh[np][3]);
                }
        }
    }

    const int rb = m0 + wm * 32 + g;
    const int cb = n0 + wn * 64 + 2 * tg;
#pragma unroll
    for (int mt = 0; mt < 2; mt++) {
#pragma unroll
        for (int nt = 0; nt < 8; nt++) {
            int r = rb + mt * 16;
            int c = cb + nt * 8;
            float v0 = acc[mt][nt][0], v1 = acc[mt][nt][1];
            float v2 = acc[mt][nt][2], v3 = acc[mt][nt][3];
            if (bias) {
                float b0 = bias[c], b1 = bias[c + 1];
                v0 += b0; v1 += b1; v2 += b0; v3 += b1;
            }
            if (resid) {
                float2 r0 = *(const float2*)&resid[(size_t)r * N + c];
                float2 r1 = *(const float2*)&resid[(size_t)(r + 8) * N + c];
                v0 += r0.x; v1 += r0.y; v2 += r1.x; v3 += r1.y;
            }
            if (OUTMODE == 0) {
                float2 o0 = {v0, v1}, o1 = {v2, v3};
                *(float2*)&C[(size_t)r * N + c]       = o0;
                *(float2*)&C[(size_t)(r + 8) * N + c] = o1;
            } else {
                __nv_bfloat162 h0 = __floats2bfloat162_rn(v0, v1);
                __nv_bfloat162 h1 = __floats2bfloat162_rn(v2, v3);
                *(__nv_bfloat162*)&Ch[(size_t)r * N + c]       = h0;
                *(__nv_bfloat162*)&Ch[(size_t)(r + 8) * N + c] = h1;
            }
        }
    }
}

// ---------------------------------------------------------------------------
// tf32 2-MMA GEMM (FFN). GS=3 ring (prefetch depth 2) + 2 CTAs/SM.
// 3 * 36864 B = 110592 B per CTA; 2 CTAs = 221184 B < 228 KB SM limit.
// ---------------------------------------------------------------------------
#define PAF   36                 // f32 pitch (144B)
#define ATF   (128 * PAF)        // f32 per operand per stage
#define STGF  (2 * ATF)          // 9216 f32 per stage
#define SMEM_T (3 * STGF * 4)    // 110592 B

template <int RELU, int TFOUT>
__global__ __launch_bounds__(256, 2)
void tf32_gemm(const float* __restrict__ A,    // [M][K]
               const float* __restrict__ Bt,   // [N][K]
               const float* __restrict__ bias,
               const float* __restrict__ resid,
               float* __restrict__ C,
               int M, int N, int K)
{
    extern __shared__ float fsm[];
    const int tid  = threadIdx.x;
    const int lane = tid & 31;
    const int warp = tid >> 5;
    const int wm   = warp >> 1;
    const int wn   = warp & 1;
    const int g    = lane >> 2;
    const int tg   = lane & 3;
    const int m0   = blockIdx.y * 128;
    const int n0   = blockIdx.x * 128;

    float acc[2][8][4];
#pragma unroll
    for (int i = 0; i < 2; i++)
#pragma unroll
        for (int j = 0; j < 8; j++)
#pragma unroll
            for (int q = 0; q < 4; q++) acc[i][j][q] = 0.f;

    const int T = K >> 5;

#define TGL(T_, S_)                                                            \
    {                                                                          \
        const int k0_ = (T_) * 32;                                             \
        float* sb_ = fsm + (S_) * STGF;                                        \
        _Pragma("unroll")                                                      \
        for (int j = 0; j < 8; j++) {                                          \
            int c = tid + 256 * j;                                             \
            if (c < 1024) {                                                    \
                int row = c >> 3, ch = c & 7;                                  \
                float* d = sb_ + row * PAF + ch * 4;                           \
                const float* s = A + (size_t)(m0 + row) * K + k0_ + ch * 4;    \
                CP_ASYNC16(sptr(d), s);                                        \
            } else {                                                           \
                int c2 = c - 1024;                                             \
                int row = c2 >> 3, ch = c2 & 7;                                \
                float* d = sb_ + ATF + row * PAF + ch * 4;                     \
                const float* s = Bt + (size_t)(n0 + row) * K + k0_ + ch * 4;   \
                CP_ASYNC16(sptr(d), s);                                        \
            }                                                                  \
        }                                                                      \
    }

    TGL(0, 0); CP_COMMIT();
    TGL(1, 1); CP_COMMIT();

    const int a_r = wm * 32 + (lane & 15);
    const int a_c = (lane >> 4) * 4;
    const int b_r = wn * 64 + (lane & 7);
    const int b_c = (lane >> 3) * 4;

    for (int t = 0; t < T; t++) {
        CP_WAITN(1);              // stage t landed; <=1 group (t+1) pending
        __syncthreads();
        if (t + 2 < T) { TGL(t + 2, (t + 2) % 3); CP_COMMIT(); }

        float* sA = fsm + (t % 3) * STGF;
        float* sB = sA + ATF;

#pragma unroll
        for (int kh = 0; kh < 32; kh += 16) {
            unsigned afr[2][2][4];
#pragma unroll
            for (int mt = 0; mt < 2; mt++)
#pragma unroll
                for (int ks = 0; ks < 2; ks++)
                    ldsm4(afr[mt][ks],
                          sptr(sA + (a_r + mt * 16) * PAF + kh + ks * 8 + a_c));
#pragma unroll
            for (int jh = 0; jh < 2; jh++) {
                unsigned bfr[4][4];
#pragma unroll
                for (int j2 = 0; j2 < 4; j2++)
                    ldsm4(bfr[j2],
                          sptr(sB + (b_r + (jh * 4 + j2) * 8) * PAF + kh + b_c));
#pragma unroll
                for (int mt = 0; mt < 2; mt++)
#pragma unroll
                    for (int j2 = 0; j2 < 4; j2++) {
                        mma_tf32(acc[mt][jh * 4 + j2], afr[mt][0],
                                 bfr[j2][0], bfr[j2][1]);
                        mma_tf32(acc[mt][jh * 4 + j2], afr[mt][1],
                                 bfr[j2][2], bfr[j2][3]);
                    }
            }
        }
    }

    const int rb = m0 + wm * 32 + g;
    const int cb = n0 + wn * 64 + 2 * tg;
#pragma unroll
    for (int mt = 0; mt < 2; mt++) {
#pragma unroll
        for (int nt = 0; nt < 8; nt++) {
            int r = rb + mt * 16;
            int c = cb + nt * 8;
            float v0 = acc[mt][nt][0], v1 = acc[mt][nt][1];
            float v2 = acc[mt][nt][2], v3 = acc[mt][nt][3];
            if (bias) {
                float b0 = bias[c], b1 = bias[c + 1];
                v0 += b0; v1 += b1; v2 += b0; v3 += b1;
            }
            if (resid) {
                float2 r0 = *(const float2*)&resid[(size_t)r * N + c];
                float2 r1 = *(const float2*)&resid[(size_t)(r + 8) * N + c];
                v0 += r0.x; v1 += r0.y; v2 += r1.x; v3 += r1.y;
            }
            if (RELU) {
                v0 = fmaxf(v0, 0.f); v1 = fmaxf(v1, 0.f);
                v2 = fmaxf(v2, 0.f); v3 = fmaxf(v3, 0.f);
            }
            if (TFOUT) {
                v0 = to_tf32(v0); v1 = to_tf32(v1);
                v2 = to_tf32(v2); v3 = to_tf32(v3);
            }
            float2 o0 = {v0, v1}, o1 = {v2, v3};
            *(float2*)&C[(size_t)r * N + c]       = o0;
            *(float2*)&C[(size_t)(r + 8) * N + c] = o1;
        }
    }
}

// ---------------------------------------------------------------------------
// Tensor-core flash attention, pure bf16, max-free fast-exp softmax. occ2.
// KV ring 3 stages (prefetch depth 2).
// smem = (128 + 6*64)*QP*2 = 73728 B per CTA; 2 CTAs fit.
// ---------------------------------------------------------------------------
#define QP 72

__global__ __launch_bounds__(256, 2)
void flash_attn_mma(const __nv_bfloat16* __restrict__ qv,
                    __nv_bfloat16* __restrict__ o)
{
    extern __shared__ __nv_bfloat16 sm[];
    __nv_bfloat16* sQ  = sm;
    __nv_bfloat16* sKV = sQ + 128 * QP;   // [3 stages][2 arrays][64][QP]

    const int q0   = blockIdx.x * 128;
    const int h    = blockIdx.y;
    const int b    = blockIdx.z;
    const int tid  = threadIdx.x;
    const int lane = tid & 31;
    const int warp = tid >> 5;
    const int g    = lane >> 2;
    const int tg   = lane & 3;

    const size_t tokbase = (size_t)b * S_;
    const int qoff = h * 64;
    const int koff = D_ + h * 64;
    const int voff = 2 * D_ + h * 64;

#pragma unroll
    for (int i = 0; i < 4; i++) {
        int c   = tid + 256 * i;
        int row = c >> 3;
        int ch  = c & 7;
        const __nv_bfloat16* src =
            qv + (tokbase + q0 + row) * NQKV + qoff + ch * 8;
        CP_ASYNC16(sptr(sQ + row * QP + ch * 8), src);
    }
    CP_COMMIT();

#define KV_LOAD(T, STG)                                                        \
    {                                                                          \
        _Pragma("unroll")                                                      \
        for (int i = 0; i < 4; i++) {                                          \
            int c   = tid + 256 * i;                                           \
            int arr = c >> 9;                                                  \
            int rem = c & 511;                                                 \
            int row = rem >> 3;                                                \
            int ch  = rem & 7;                                                 \
            const __nv_bfloat16* src =                                         \
                qv + (tokbase + (T) * 64 + row) * NQKV                         \
                   + (arr ? voff : koff) + ch * 8;                             \
            __nv_bfloat16* dst =                                               \
                sKV + ((STG) * 2 + arr) * (64 * QP) + row * QP + ch * 8;       \
            CP_ASYNC16(sptr(dst), src);                                        \
        }                                                                      \
    }

    KV_LOAD(0, 0);
    CP_COMMIT();
    KV_LOAD(1, 1);
    CP_COMMIT();

    CP_WAITN(2);          // Q landed (KV0/KV1 may be pending)
    __syncthreads();

    unsigned qf[4][4];
    {
        const int a_r = warp * 16 + (lane & 15);
        const int a_c = (lane >> 4) * 8;
#pragma unroll
        for (int ks = 0; ks < 4; ks++)
            ldsm4(qf[ks], sptr(sQ + a_r * QP + ks * 16 + a_c));
    }

    float accO[8][4];
#pragma unroll
    for (int j = 0; j < 8; j++)
#pragma unroll
        for (int q = 0; q < 4; q++) accO[j][q] = 0.f;
    float l0r = 0.f, l1r = 0.f;

    const int nTiles = S_ / 64;
    for (int t = 0; t < nTiles; t++) {
        CP_WAITN(1);      // tile t landed; <=1 group (t+1) pending
        __syncthreads();
        if (t + 2 < nTiles) {
            KV_LOAD(t + 2, (t + 2) % 3);
            CP_COMMIT();
        }

        const __nv_bfloat16* K_ = sKV + ((t % 3) * 2 + 0) * (64 * QP);
        const __nv_bfloat16* V_ = sKV + ((t % 3) * 2 + 1) * (64 * QP);

        float sc[8][4];
#pragma unroll
        for (int j = 0; j < 8; j++)
#pragma unroll
            for (int q = 0; q < 4; q++) sc[j][q] = 0.f;

#pragma unroll
        for (int ks = 0; ks < 4; ks++) {
#pragma unroll
            for (int ng = 0; ng < 4; ng++) {
                unsigned kh[4];
                ldsm4(kh, sptr(K_ + (ng * 16 + (lane & 15)) * QP
                                  + ks * 16 + (lane >> 4) * 8));
                mma_bf16(sc[2 * ng],     qf[ks], kh[0], kh[2]);
                mma_bf16(sc[2 * ng + 1], qf[ks], kh[1], kh[3]);
            }
        }

#pragma unroll
        for (int j = 0; j < 8; j++) {
            sc[j][0] = fexp8(sc[j][0]);
            sc[j][1] = fexp8(sc[j][1]);
            sc[j][2] = fexp8(sc[j][2]);
            sc[j][3] = fexp8(sc[j][3]);
            l0r += sc[j][0] + sc[j][1];
            l1r += sc[j][2] + sc[j][3];
        }

#pragma unroll
        for (int ks = 0; ks < 4; ks++) {
            unsigned pa[4];
            {
                float* p0 = sc[2 * ks];
                float* p1 = sc[2 * ks + 1];
                pa[0] = bf2u(__floats2bfloat162_rn(p0[0], p0[1]));
                pa[1] = bf2u(__floats2bfloat162_rn(p0[2], p0[3]));
                pa[2] = bf2u(__floats2bfloat162_rn(p1[0], p1[1]));
                pa[3] = bf2u(__floats2bfloat162_rn(p1[2], p1[3]));
            }
#pragma unroll
            for (int ng = 0; ng < 4; ng++) {
                unsigned vh[4];
                ldsm4t(vh, sptr(V_ + (ks * 16 + (lane & 15)) * QP
                                   + ng * 16 + (lane >> 4) * 8));
                mma_bf16(accO[2 * ng],     pa, vh[0], vh[1]);
                mma_bf16(accO[2 * ng + 1], pa, vh[2], vh[3]);
            }
        }
    }

    l0r += __shfl_xor_sync(0xffffffffu, l0r, 1);
    l0r += __shfl_xor_sync(0xffffffffu, l0r, 2);
    l1r += __shfl_xor_sync(0xffffffffu, l1r, 1);
    l1r += __shfl_xor_sync(0xffffffffu, l1r, 2);

    const float inv0 = 1.f / l0r;
    const float inv1 = 1.f / l1r;
    const size_t r0 = tokbase + q0 + warp * 16 + g;
    const size_t r1 = r0 + 8;
    const int cbase = h * 64 + 2 * tg;
#pragma unroll
    for (int nt = 0; nt < 8; nt++) {
        int c = cbase + nt * 8;
        __nv_bfloat162 h0 = __floats2bfloat162_rn(accO[nt][0] * inv0,
                                                  accO[nt][1] * inv0);
        __nv_bfloat162 h1 = __floats2bfloat162_rn(accO[nt][2] * inv1,
                                                  accO[nt][3] * inv1);
        *(__nv_bfloat162*)&o[r0 * D_ + c] = h0;
        *(__nv_bfloat162*)&o[r1 * D_ + c] = h1;
    }
}

// ---------------------------------------------------------------------------
// LayerNorm over last dim (D=1024), float4-vectorized.
// MODE 1: also emit tf32-rounded f32 copy.
// ---------------------------------------------------------------------------
template <int MODE>
__global__ __launch_bounds__(256)
void layernorm_kernel(const float* __restrict__ x, const float* __restrict__ gw,
                      const float* __restrict__ bw, float* __restrict__ out,
                      float* __restrict__ outT)
{
    __shared__ float rs[8], rs2[8];
    const int row = blockIdx.x;
    const int tid = threadIdx.x;

    float4 v = ((const float4*)(x + (size_t)row * D_))[tid];
    float s  = v.x + v.y + v.z + v.w;
    float s2 = v.x * v.x + v.y * v.y + v.z * v.z + v.w * v.w;
#pragma unroll
    for (int off = 16; off; off >>= 1) {
        s  += __shfl_xor_sync(0xffffffffu, s,  off);
        s2 += __shfl_xor_sync(0xffffffffu, s2, off);
    }
    if ((tid & 31) == 0) { rs[tid >> 5] = s; rs2[tid >> 5] = s2; }
    __syncthreads();
    float ts = 0.f, ts2 = 0.f;
#pragma unroll
    for (int i = 0; i < 8; i++) { ts += rs[i]; ts2 += rs2[i]; }

    const float mu  = ts * (1.0f / D_);
    const float var = ts2 * (1.0f / D_) - mu * mu;
    const float inv = rsqrtf(var + 1e-5f);

    float4 gg = ((const float4*)gw)[tid];
    float4 bb = ((const float4*)bw)[tid];
    float4 o;
    o.x = (v.x - mu) * inv * gg.x + bb.x;
    o.y = (v.y - mu) * inv * gg.y + bb.y;
    o.z = (v.z - mu) * inv * gg.z + bb.z;
    o.w = (v.w - mu) * inv * gg.w + bb.w;
    ((float4*)(out + (size_t)row * D_))[tid] = o;
    if (MODE) {
        float4 ot;
        ot.x = to_tf32(o.x); ot.y = to_tf32(o.y);
        ot.z = to_tf32(o.z); ot.w = to_tf32(o.w);
        ((float4*)(outT + (size_t)row * D_))[tid] = ot;
    }
}

// ---------------------------------------------------------------------------
// kernel_launch
// Inputs: x wq bq wk bk wv bv wo bo ln1_g ln1_b w1 b1 w2 b2 ln2_g ln2_b
// Side stream carries FFN/WO weight prep, overlapped with QKV+attention.
// ---------------------------------------------------------------------------
extern "C" void kernel_launch(void* const* d_in, const int* in_sizes, int n_in,
                              void* d_out, int out_size)
{
    (void)in_sizes; (void)n_in; (void)out_size;
    const float* x     = (const float*)d_in[0];
    const float* wq    = (const float*)d_in[1];
    const float* bq    = (const float*)d_in[2];
    const float* wk    = (const float*)d_in[3];
    const float* bk    = (const float*)d_in[4];
    const float* wv    = (const float*)d_in[5];
    const float* bv    = (const float*)d_in[6];
    const float* wo    = (const float*)d_in[7];
    const float* bo    = (const float*)d_in[8];
    const float* ln1g  = (const float*)d_in[9];
    const float* ln1b  = (const float*)d_in[10];
    const float* w1    = (const float*)d_in[11];
    const float* b1    = (const float*)d_in[12];
    const float* w2    = (const float*)d_in[13];
    const float* b2    = (const float*)d_in[14];
    const float* ln2g  = (const float*)d_in[15];
    const float* ln2b  = (const float*)d_in[16];
    float* out = (float*)d_out;

    float *tmp, *y, *ytf, *ff, *bqkv, *w1t, *w2t;
    __nv_bfloat16 *xh, *qkv, *attn, *wqkvh, *woh;
    cudaGetSymbolAddress((void**)&tmp,   g_tmp);
    cudaGetSymbolAddress((void**)&y,     g_y);
    cudaGetSymbolAddress((void**)&ytf,   g_ytf);
    cudaGetSymbolAddress((void**)&ff,    g_ff);
    cudaGetSymbolAddress((void**)&bqkv,  g_bqkv);
    cudaGetSymbolAddress((void**)&w1t,   g_w1t);
    cudaGetSymbolAddress((void**)&w2t,   g_w2t);
    cudaGetSymbolAddress((void**)&xh,    g_x_h);
    cudaGetSymbolAddress((void**)&qkv,   g_qkv);
    cudaGetSymbolAddress((void**)&attn,  g_attn);
    cudaGetSymbolAddress((void**)&wqkvh, g_wqkv_h);
    cudaGetSymbolAddress((void**)&woh,   g_wo_h);

    cudaFuncSetAttribute(mma_gemm_b16<1>,
        cudaFuncAttributeMaxDynamicSharedMemorySize, SMEM_1);
    cudaFuncSetAttribute(mma_gemm_b16<0>,
        cudaFuncAttributeMaxDynamicSharedMemorySize, SMEM_1);
    cudaFuncSetAttribute(tf32_gemm<1, 1>,
        cudaFuncAttributeMaxDynamicSharedMemorySize, SMEM_T);
    cudaFuncSetAttribute(tf32_gemm<0, 0>,
        cudaFuncAttributeMaxDynamicSharedMemorySize, SMEM_T);

    // Side stream for weight prep that is needed only later (WO / FFN).
    cudaStream_t s2;
    cudaStreamCreateWithFlags(&s2, cudaStreamNonBlocking);
    cudaEvent_t eFork, eJoin;
    cudaEventCreateWithFlags(&eFork, cudaEventDisableTiming);
    cudaEventCreateWithFlags(&eJoin, cudaEventDisableTiming);

    // Main stream: prep needed for QKV
    size_t nx4 = (size_t)NTOK * D_ / 4;
    tobf16_v4<<<(unsigned)((nx4 + 255) / 256), 256>>>(x, xh, nx4);
    pack_qkv_b<<<(NQKV + 255) / 256, 256>>>(bq, bk, bv, bqkv);
    size_t nq4 = (size_t)D_ * NQKV / 4;
    pack_qkv_w4<<<(unsigned)((nq4 + 255) / 256), 256>>>(wq, wk, wv, wqkvh);

    // Fork: wo convert + FFN weight transposes on s2 (consumed after attn)
    cudaEventRecord(eFork, 0);
    cudaStreamWaitEvent(s2, eFork, 0);
    size_t nwo4 = (size_t)D_ * D_ / 4;
    tobf16_v4<<<(unsigned)((nwo4 + 255) / 256), 256, 0, s2>>>(wo, woh, nwo4);
    transpose_tf32<<<dim3(F_ / 32, D_ / 32), dim3(32, 8), 0, s2>>>(
        w1, w1t, D_, F_);
    transpose_tf32<<<dim3(D_ / 32, F_ / 32), dim3(32, 8), 0, s2>>>(
        w2, w2t, F_, D_);
    cudaEventRecord(eJoin, s2);

    // Main: QKV projection (bf16) -> fused bf16 buffer
    mma_gemm_b16<1><<<dim3(NQKV / 128, NTOK / 128), 256, SMEM_1>>>(
        xh, wqkvh, bqkv, nullptr, nullptr, qkv, NTOK, NQKV, D_);

    // Main: flash attention -> concat heads bf16
    {
        size_t smem = (size_t)(128 + 6 * 64) * QP * sizeof(__nv_bfloat16);
        cudaFuncSetAttribute(flash_attn_mma,
                             cudaFuncAttributeMaxDynamicSharedMemorySize, (int)smem);
        flash_attn_mma<<<dim3(S_ / 128, H_, B_), 256, smem>>>(qkv, attn);
    }

    // Join side stream before consuming woh / w1t / w2t
    cudaStreamWaitEvent(0, eJoin, 0);

    // Output projection (bf16) + bias + residual(x) -> f32 tmp
    mma_gemm_b16<0><<<dim3(D_ / 128, NTOK / 128), 256, SMEM_1>>>(
        attn, woh, bo, x, tmp, nullptr, NTOK, D_, D_);

    // LayerNorm 1 -> y (exact f32) + ytf (tf32)
    layernorm_kernel<1><<<NTOK, 256>>>(tmp, ln1g, ln1b, y, ytf);

    // FFN up (tf32, occ2, GS=3): relu(y @ w1 + b1) -> ff
    tf32_gemm<1, 1><<<dim3(F_ / 128, NTOK / 128), 256, SMEM_T>>>(
        ytf, w1t, b1, nullptr, ff, NTOK, F_, D_);

    // FFN down (tf32, occ2, GS=3) + bias + residual(y) -> f32 tmp
    tf32_gemm<0, 0><<<dim3(D_ / 128, NTOK / 128), 256, SMEM_T>>>(
        ff, w2t, b2, y, tmp, NTOK, D_, F_);

    // LayerNorm 2 -> output
    layernorm_kernel<0><<<NTOK, 256>>>(tmp, ln2g, ln2b, out, nullptr);
}

// round 17
// speedup vs baseline: 1.0019x; 1.0019x over previous
#include <cuda_runtime.h>
#include <cuda_bf16.h>
#include <math.h>

// Problem constants
#define B_    4
#define S_    2048
#define D_    1024
#define H_    16
#define DH_   64
#define F_    4096
#define NTOK  (B_ * S_)        // 8192 tokens
#define NQKV  (3 * D_)         // 3072 fused qkv columns

// ---------------------------------------------------------------------------
// Scratch (static device globals — no runtime allocation allowed)
// ---------------------------------------------------------------------------
static __device__ __align__(256) __nv_bfloat16 g_x_h [(size_t)NTOK * D_];
static __device__ __align__(256) __nv_bfloat16 g_qkv [(size_t)NTOK * NQKV];
static __device__ __align__(256) __nv_bfloat16 g_attn[(size_t)NTOK * D_];
static __device__ float g_tmp [(size_t)NTOK * D_];    // residual sums pre-LN
static __device__ float g_y   [(size_t)NTOK * D_];    // LN1 output (exact f32)
static __device__ __align__(256) float g_ytf[(size_t)NTOK * D_];  // tf32 copy
static __device__ __align__(256) float g_ff [(size_t)NTOK * F_];  // FFN hidden (tf32)
static __device__ float g_bqkv[NQKV];                 // packed qkv bias

// bf16 weights for QKV/WO; tf32-rounded transposed weights for FFN
static __device__ __align__(256) __nv_bfloat16 g_wqkv_h[(size_t)D_ * NQKV];
static __device__ __align__(256) __nv_bfloat16 g_wo_h[(size_t)D_ * D_];
static __device__ __align__(256) float g_w1t[(size_t)F_ * D_];   // [F][D]
static __device__ __align__(256) float g_w2t[(size_t)D_ * F_];   // [D][F]

// ---------------------------------------------------------------------------
// PTX helpers
// ---------------------------------------------------------------------------
static __device__ __forceinline__ unsigned sptr(const void* p) {
    return (unsigned)__cvta_generic_to_shared(p);
}
static __device__ __forceinline__ void ldsm4(unsigned* r, unsigned addr) {
    asm volatile("ldmatrix.sync.aligned.m8n8.x4.shared.b16 {%0,%1,%2,%3}, [%4];"
                 : "=r"(r[0]), "=r"(r[1]), "=r"(r[2]), "=r"(r[3]) : "r"(addr));
}
static __device__ __forceinline__ void ldsm4t(unsigned* r, unsigned addr) {
    asm volatile("ldmatrix.sync.aligned.m8n8.x4.trans.shared.b16 {%0,%1,%2,%3}, [%4];"
                 : "=r"(r[0]), "=r"(r[1]), "=r"(r[2]), "=r"(r[3]) : "r"(addr));
}
static __device__ __forceinline__ void mma_bf16(float* c, const unsigned* a,
                                                unsigned b0, unsigned b1) {
    asm volatile(
        "mma.sync.aligned.m16n8k16.row.col.f32.bf16.bf16.f32 "
        "{%0,%1,%2,%3}, {%4,%5,%6,%7}, {%8,%9}, {%0,%1,%2,%3};"
        : "+f"(c[0]), "+f"(c[1]), "+f"(c[2]), "+f"(c[3])
        : "r"(a[0]), "r"(a[1]), "r"(a[2]), "r"(a[3]), "r"(b0), "r"(b1));
}
static __device__ __forceinline__ void mma_tf32(float* c, const unsigned* a,
                                                unsigned b0, unsigned b1) {
    asm volatile(
        "mma.sync.aligned.m16n8k8.row.col.f32.tf32.tf32.f32 "
        "{%0,%1,%2,%3}, {%4,%5,%6,%7}, {%8,%9}, {%0,%1,%2,%3};"
        : "+f"(c[0]), "+f"(c[1]), "+f"(c[2]), "+f"(c[3])
        : "r"(a[0]), "r"(a[1]), "r"(a[2]), "r"(a[3]), "r"(b0), "r"(b1));
}
static __device__ __forceinline__ float to_tf32(float x) {
    unsigned u;
    asm("cvt.rna.tf32.f32 %0, %1;" : "=r"(u) : "f"(x));
    return __uint_as_float(u);
}
// Fast exp for softmax weights (Schraudolph), 1/8 scale folded in.
static __device__ __forceinline__ float fexp8(float s) {
    return __int_as_float(__float2int_rn(fmaf(s, 1512775.395f, 1064986823.0f)));
}
#define CP_ASYNC16(dst, src) \
    asm volatile("cp.async.cg.shared.global [%0], [%1], 16;" :: "r"(dst), "l"(src))
#define CP_COMMIT() asm volatile("cp.async.commit_group;")
#define CP_WAITN(N) asm volatile("cp.async.wait_group %0;" :: "n"(N))

static __device__ __forceinline__ unsigned bf2u(__nv_bfloat162 v) {
    return *reinterpret_cast<unsigned*>(&v);
}

// ---------------------------------------------------------------------------
// Prep kernels
// ---------------------------------------------------------------------------
__global__ void tobf16_v4(const float* __restrict__ w,
                          __nv_bfloat16* __restrict__ oh, size_t n4)
{
    size_t i = (size_t)blockIdx.x * 256 + threadIdx.x;
    if (i >= n4) return;
    float4 v = ((const float4*)w)[i];
    __nv_bfloat162 a = __floats2bfloat162_rn(v.x, v.y);
    __nv_bfloat162 b = __floats2bfloat162_rn(v.z, v.w);
    ((uint2*)oh)[i] = make_uint2(bf2u(a), bf2u(b));
}

// wq/wk/wv [H,D,DH] -> [K=1024, N=3072] row-major bf16 (vectorized x4)
__global__ void pack_qkv_w4(const float* __restrict__ wq,
                            const float* __restrict__ wk,
                            const float* __restrict__ wv,
                            __nv_bfloat16* __restrict__ oh)
{
    size_t i = (size_t)blockIdx.x * 256 + threadIdx.x;
    if (i >= (size_t)D_ * NQKV / 4) return;
    size_t idx = i * 4;
    int d  = (int)(idx / NQKV);
    int j  = (int)(idx % NQKV);
    int p  = j / D_;
    int he = j % D_;
    int h  = he >> 6;
    int e  = he & 63;
    const float* w = (p == 0) ? wq : ((p == 1) ? wk : wv);
    float4 v = *(const float4*)&w[(size_t)h * D_ * DH_ + (size_t)d * DH_ + e];
    __nv_bfloat162 a = __floats2bfloat162_rn(v.x, v.y);
    __nv_bfloat162 b = __floats2bfloat162_rn(v.z, v.w);
    *(uint2*)&oh[idx] = make_uint2(bf2u(a), bf2u(b));
}

__global__ void pack_qkv_b(const float* __restrict__ bq,
                           const float* __restrict__ bk,
                           const float* __restrict__ bv,
                           float* __restrict__ out)
{
    int j = blockIdx.x * 256 + threadIdx.x;
    if (j >= NQKV) return;
    int p  = j / D_;
    int he = j % D_;
    const float* b = (p == 0) ? bq : ((p == 1) ? bk : bv);
    out[j] = b[he];
}

// src [K][N] f32 -> dst [N][K] f32, tf32-rounded (tiled transpose)
__global__ void transpose_tf32(const float* __restrict__ src,
                               float* __restrict__ dst, int K, int N)
{
    __shared__ float t[32][33];
    const int n0 = blockIdx.x * 32;
    const int k0 = blockIdx.y * 32;
    const int tx = threadIdx.x, ty = threadIdx.y;
#pragma unroll
    for (int i = 0; i < 4; i++)
        t[ty + 8 * i][tx] = src[(size_t)(k0 + ty + 8 * i) * N + n0 + tx];
    __syncthreads();
#pragma unroll
    for (int i = 0; i < 4; i++)
        dst[(size_t)(n0 + ty + 8 * i) * K + k0 + tx] = to_tf32(t[tx][ty + 8 * i]);
}

// ---------------------------------------------------------------------------
// bf16 1-MMA GEMM (QKV / WO). occ2, GS=3. (R14 best-measured config)
// ---------------------------------------------------------------------------
#define PA2   40
#define PB2   136
#define A_T   (128 * PA2)
#define B_T   (32 * PB2)
#define SMEM_1 (3 * (A_T + B_T) * 2)       // 56832 B

template <int OUTMODE>
__global__ __launch_bounds__(256, 2)
void mma_gemm_b16(const __nv_bfloat16* __restrict__ Ah,
                  const __nv_bfloat16* __restrict__ Bh,
                  const float* __restrict__ bias,
                  const float* __restrict__ resid,
                  float* __restrict__ C,
                  __nv_bfloat16* __restrict__ Ch,
                  int M, int N, int K)
{
    extern __shared__ __nv_bfloat16 dsm[];
    constexpr int STG = A_T + B_T;

    const int tid  = threadIdx.x;
    const int lane = tid & 31;
    const int warp = tid >> 5;
    const int wm   = warp >> 1;
    const int wn   = warp & 1;
    const int g    = lane >> 2;
    const int tg   = lane & 3;
    const int m0   = blockIdx.y * 128;
    const int n0   = blockIdx.x * 128;

    float acc[2][8][4];
#pragma unroll
    for (int i = 0; i < 2; i++)
#pragma unroll
        for (int j = 0; j < 8; j++)
#pragma unroll
            for (int q = 0; q < 4; q++) acc[i][j][q] = 0.f;

    const int T = K >> 5;

#define GLB(T_, S_)                                                            \
    {                                                                          \
        const int k0_ = (T_) * 32;                                             \
        __nv_bfloat16* sb_ = dsm + (S_) * STG;                                 \
        _Pragma("unroll")                                                      \
        for (int j = 0; j < 4; j++) {                                          \
            int c = tid + 256 * j;                                             \
            if (c < 512) {                                                     \
                int row = c >> 2, ch = c & 3;                                  \
                __nv_bfloat16* d = sb_ + row * PA2 + ch * 8;                   \
                const __nv_bfloat16* s =                                       \
                    Ah + (size_t)(m0 + row) * K + k0_ + ch * 8;                \
                CP_ASYNC16(sptr(d), s);                                        \
            } else {                                                           \
                int c2 = c - 512;                                              \
                int row = c2 >> 4, ch = c2 & 15;                               \
                __nv_bfloat16* d = sb_ + A_T + row * PB2 + ch * 8;             \
                const __nv_bfloat16* s =                                       \
                    Bh + (size_t)(k0_ + row) * N + n0 + ch * 8;                \
                CP_ASYNC16(sptr(d), s);                                        \
            }                                                                  \
        }                                                                      \
    }

    GLB(0, 0); CP_COMMIT();
    GLB(1, 1); CP_COMMIT();

    const int a_r  = wm * 32 + (lane & 15);
    const int a_kc = (lane >> 4) * 8;
    const int b_k  = (lane & 15);
    const int b_nc = wn * 64 + (lane >> 4) * 8;

    for (int t = 0; t < T; t++) {
        CP_WAITN(1);
        __syncthreads();
        __nv_bfloat16* sAh = dsm + (t % 3) * STG;
        __nv_bfloat16* sBh = sAh + A_T;

#pragma unroll
        for (int kk = 0; kk < 32; kk += 16) {
            unsigned ah[2][4], bh[4][4];
#pragma unroll
            for (int mt = 0; mt < 2; mt++)
                ldsm4(ah[mt], sptr(sAh + (a_r + mt * 16) * PA2 + kk + a_kc));
#pragma unroll
            for (int np = 0; np < 4; np++)
                ldsm4t(bh[np], sptr(sBh + (kk + b_k) * PB2 + b_nc + np * 16));
#pragma unroll
            for (int mt = 0; mt < 2; mt++)
#pragma unroll
                for (int np = 0; np < 4; np++) {
                    mma_bf16(acc[mt][2 * np],     ah[mt], bh[np][0], bh[np][1]);
                    mma_bf16(acc[mt][2 * np + 1], ah[mt], bh[np][2], bh[np][3]);
                }
        }

        if (t + 2 < T) GLB(t + 2, (t + 2) % 3);
        CP_COMMIT();
    }

    const int rb = m0 + wm * 32 + g;
    const int cb = n0 + wn * 64 + 2 * tg;
#pragma unroll
    for (int mt = 0; mt < 2; mt++) {
#pragma unroll
        for (int nt = 0; nt < 8; nt++) {
            int r = rb + mt * 16;
            int c = cb + nt * 8;
            float v0 = acc[mt][nt][0], v1 = acc[mt][nt][1];
            float v2 = acc[mt][nt][2], v3 = acc[mt][nt][3];
            if (bias) {
                float b0 = bias[c], b1 = bias[c + 1];
                v0 += b0; v1 += b1; v2 += b0; v3 += b1;
            }
            if (resid) {
                float2 r0 = *(const float2*)&resid[(size_t)r * N + c];
                float2 r1 = *(const float2*)&resid[(size_t)(r + 8) * N + c];
                v0 += r0.x; v1 += r0.y; v2 += r1.x; v3 += r1.y;
            }
            if (OUTMODE == 0) {
                float2 o0 = {v0, v1}, o1 = {v2, v3};
                *(float2*)&C[(size_t)r * N + c]       = o0;
                *(float2*)&C[(size_t)(r + 8) * N + c] = o1;
            } else {
                __nv_bfloat162 h0 = __floats2bfloat162_rn(v0, v1);
                __nv_bfloat162 h1 = __floats2bfloat162_rn(v2, v3);
                *(__nv_bfloat162*)&Ch[(size_t)r * N + c]       = h0;
                *(__nv_bfloat162*)&Ch[(size_t)(r + 8) * N + c] = h1;
            }
        }
    }
}

// ---------------------------------------------------------------------------
// tf32 2-MMA GEMM (FFN). GS=2 double buffer + 2 CTAs/SM. (R14 config)
// ---------------------------------------------------------------------------
#define PAF   36                 // f32 pitch (144B)
#define ATF   (128 * PAF)        // f32 per operand per stage
#define STGF  (2 * ATF)          // 9216 f32 per stage
#define SMEM_T (2 * STGF * 4)    // 73728 B -> 2 CTAs/SM

template <int RELU, int TFOUT>
__global__ __launch_bounds__(256, 2)
void tf32_gemm(const float* __restrict__ A,    // [M][K]
               const float* __restrict__ Bt,   // [N][K]
               const float* __restrict__ bias,
               const float* __restrict__ resid,
               float* __restrict__ C,
               int M, int N, int K)
{
    extern __shared__ float fsm[];
    const int tid  = threadIdx.x;
    const int lane = tid & 31;
    const int warp = tid >> 5;
    const int wm   = warp >> 1;
    const int wn   = warp & 1;
    const int g    = lane >> 2;
    const int tg   = lane & 3;
    const int m0   = blockIdx.y * 128;
    const int n0   = blockIdx.x * 128;

    float acc[2][8][4];
#pragma unroll
    for (int i = 0; i < 2; i++)
#pragma unroll
        for (int j = 0; j < 8; j++)
#pragma unroll
            for (int q = 0; q < 4; q++) acc[i][j][q] = 0.f;

    const int T = K >> 5;

#define TGL(T_, S_)                                                            \
    {                                                                          \
        const int k0_ = (T_) * 32;                                             \
        float* sb_ = fsm + (S_) * STGF;                                        \
        _Pragma("unroll")                                                      \
        for (int j = 0; j < 8; j++) {                                          \
            int c = tid + 256 * j;                                             \
            if (c < 1024) {                                                    \
                int row = c >> 3, ch = c & 7;                                  \
                float* d = sb_ + row * PAF + ch * 4;                           \
                const float* s = A + (size_t)(m0 + row) * K + k0_ + ch * 4;    \
                CP_ASYNC16(sptr(d), s);                                        \
            } else {                                                           \
                int c2 = c - 1024;                                             \
                int row = c2 >> 3, ch = c2 & 7;                                \
                float* d = sb_ + ATF + row * PAF + ch * 4;                     \
                const float* s = Bt + (size_t)(n0 + row) * K + k0_ + ch * 4;   \
                CP_ASYNC16(sptr(d), s);                                        \
            }                                                                  \
        }                                                                      \
    }

    TGL(0, 0); CP_COMMIT();

    const int a_r = wm * 32 + (lane & 15);
    const int a_c = (lane >> 4) * 4;
    const int b_r = wn * 64 + (lane & 7);
    const int b_c = (lane >> 3) * 4;

    for (int t = 0; t < T; t++) {
        CP_WAITN(0);
        __syncthreads();
        if (t + 1 < T) { TGL(t + 1, (t + 1) & 1); CP_COMMIT(); }

        float* sA = fsm + (t & 1) * STGF;
        float* sB = sA + ATF;

#pragma unroll
        for (int kh = 0; kh < 32; kh += 16) {
            unsigned afr[2][2][4];
#pragma unroll
            for (int mt = 0; mt < 2; mt++)
#pragma unroll
                for (int ks = 0; ks < 2; ks++)
                    ldsm4(afr[mt][ks],
                          sptr(sA + (a_r + mt * 16) * PAF + kh + ks * 8 + a_c));
#pragma unroll
            for (int jh = 0; jh < 2; jh++) {
                unsigned bfr[4][4];
#pragma unroll
                for (int j2 = 0; j2 < 4; j2++)
                    ldsm4(bfr[j2],
                          sptr(sB + (b_r + (jh * 4 + j2) * 8) * PAF + kh + b_c));
#pragma unroll
                for (int mt = 0; mt < 2; mt++)
#pragma unroll
                    for (int j2 = 0; j2 < 4; j2++) {
                        mma_tf32(acc[mt][jh * 4 + j2], afr[mt][0],
                                 bfr[j2][0], bfr[j2][1]);
                        mma_tf32(acc[mt][jh * 4 + j2], afr[mt][1],
                                 bfr[j2][2], bfr[j2][3]);
                    }
            }
        }
    }

    const int rb = m0 + wm * 32 + g;
    const int cb = n0 + wn * 64 + 2 * tg;
#pragma unroll
    for (int mt = 0; mt < 2; mt++) {
#pragma unroll
        for (int nt = 0; nt < 8; nt++) {
            int r = rb + mt * 16;
            int c = cb + nt * 8;
            float v0 = acc[mt][nt][0], v1 = acc[mt][nt][1];
            float v2 = acc[mt][nt][2], v3 = acc[mt][nt][3];
            if (bias) {
                float b0 = bias[c], b1 = bias[c + 1];
                v0 += b0; v1 += b1; v2 += b0; v3 += b1;
            }
            if (resid) {
                float2 r0 = *(const float2*)&resid[(size_t)r * N + c];
                float2 r1 = *(const float2*)&resid[(size_t)(r + 8) * N + c];
                v0 += r0.x; v1 += r0.y; v2 += r1.x; v3 += r1.y;
            }
            if (RELU) {
                v0 = fmaxf(v0, 0.f); v1 = fmaxf(v1, 0.f);
                v2 = fmaxf(v2, 0.f); v3 = fmaxf(v3, 0.f);
            }
            if (TFOUT) {
                v0 = to_tf32(v0); v1 = to_tf32(v1);
                v2 = to_tf32(v2); v3 = to_tf32(v3);
            }
            float2 o0 = {v0, v1}, o1 = {v2, v3};
            *(float2*)&C[(size_t)r * N + c]       = o0;
            *(float2*)&C[(size_t)(r + 8) * N + c] = o1;
        }
    }
}

// ---------------------------------------------------------------------------
// Tensor-core flash attention, pure bf16, max-free fast-exp softmax. occ2.
// 2-stage KV ring. (R14 best-measured config)
// ---------------------------------------------------------------------------
#define QP 72

__global__ __launch_bounds__(256, 2)
void flash_attn_mma(const __nv_bfloat16* __restrict__ qv,
                    __nv_bfloat16* __restrict__ o)
{
    extern __shared__ __nv_bfloat16 sm[];
    __nv_bfloat16* sQ  = sm;
    __nv_bfloat16* sKV = sQ + 128 * QP;

    const int q0   = blockIdx.x * 128;
    const int h    = blockIdx.y;
    const int b    = blockIdx.z;
    const int tid  = threadIdx.x;
    const int lane = tid & 31;
    const int warp = tid >> 5;
    const int g    = lane >> 2;
    const int tg   = lane & 3;

    const size_t tokbase = (size_t)b * S_;
    const int qoff = h * 64;
    const int koff = D_ + h * 64;
    const int voff = 2 * D_ + h * 64;

#pragma unroll
    for (int i = 0; i < 4; i++) {
        int c   = tid + 256 * i;
        int row = c >> 3;
        int ch  = c & 7;
        const __nv_bfloat16* src =
            qv + (tokbase + q0 + row) * NQKV + qoff + ch * 8;
        CP_ASYNC16(sptr(sQ + row * QP + ch * 8), src);
    }
    CP_COMMIT();

#define KV_LOAD(T, STG)                                                        \
    {                                                                          \
        _Pragma("unroll")                                                      \
        for (int i = 0; i < 4; i++) {                                          \
            int c   = tid + 256 * i;                                           \
            int arr = c >> 9;                                                  \
            int rem = c & 511;                                                 \
            int row = rem >> 3;                                                \
            int ch  = rem & 7;                                                 \
            const __nv_bfloat16* src =                                         \
                qv + (tokbase + (T) * 64 + row) * NQKV                         \
                   + (arr ? voff : koff) + ch * 8;                             \
            __nv_bfloat16* dst =                                               \
                sKV + ((STG) * 2 + arr) * (64 * QP) + row * QP + ch * 8;       \
            CP_ASYNC16(sptr(dst), src);                                        \
        }                                                                      \
    }

    KV_LOAD(0, 0);
    CP_COMMIT();

    CP_WAITN(1);
    __syncthreads();

    unsigned qf[4][4];
    {
        const int a_r = warp * 16 + (lane & 15);
        const int a_c = (lane >> 4) * 8;
#pragma unroll
        for (int ks = 0; ks < 4; ks++)
            ldsm4(qf[ks], sptr(sQ + a_r * QP + ks * 16 + a_c));
    }

    float accO[8][4];
#pragma unroll
    for (int j = 0; j < 8; j++)
#pragma unroll
        for (int q = 0; q < 4; q++) accO[j][q] = 0.f;
    float l0r = 0.f, l1r = 0.f;

    const int nTiles = S_ / 64;
    for (int t = 0; t < nTiles; t++) {
        CP_WAITN(0);
        __syncthreads();
        if (t + 1 < nTiles) {
            KV_LOAD(t + 1, (t + 1) & 1);
            CP_COMMIT();
        }

        const __nv_bfloat16* K_ = sKV + ((t & 1) * 2 + 0) * (64 * QP);
        const __nv_bfloat16* V_ = sKV + ((t & 1) * 2 + 1) * (64 * QP);

        float sc[8][4];
#pragma unroll
        for (int j = 0; j < 8; j++)
#pragma unroll
            for (int q = 0; q < 4; q++) sc[j][q] = 0.f;

#pragma unroll
        for (int ks = 0; ks < 4; ks++) {
#pragma unroll
            for (int ng = 0; ng < 4; ng++) {
                unsigned kh[4];
                ldsm4(kh, sptr(K_ + (ng * 16 + (lane & 15)) * QP
                                  + ks * 16 + (lane >> 4) * 8));
                mma_bf16(sc[2 * ng],     qf[ks], kh[0], kh[2]);
                mma_bf16(sc[2 * ng + 1], qf[ks], kh[1], kh[3]);
            }
        }

#pragma unroll
        for (int j = 0; j < 8; j++) {
            sc[j][0] = fexp8(sc[j][0]);
            sc[j][1] = fexp8(sc[j][1]);
            sc[j][2] = fexp8(sc[j][2]);
            sc[j][3] = fexp8(sc[j][3]);
            l0r += sc[j][0] + sc[j][1];
            l1r += sc[j][2] + sc[j][3];
        }

#pragma unroll
        for (int ks = 0; ks < 4; ks++) {
            unsigned pa[4];
            {
                float* p0 = sc[2 * ks];
                float* p1 = sc[2 * ks + 1];
                pa[0] = bf2u(__floats2bfloat162_rn(p0[0], p0[1]));
                pa[1] = bf2u(__floats2bfloat162_rn(p0[2], p0[3]));
                pa[2] = bf2u(__floats2bfloat162_rn(p1[0], p1[1]));
                pa[3] = bf2u(__floats2bfloat162_rn(p1[2], p1[3]));
            }
#pragma unroll
            for (int ng = 0; ng < 4; ng++) {
                unsigned vh[4];
                ldsm4t(vh, sptr(V_ + (ks * 16 + (lane & 15)) * QP
                                   + ng * 16 + (lane >> 4) * 8));
                mma_bf16(accO[2 * ng],     pa, vh[0], vh[1]);
                mma_bf16(accO[2 * ng + 1], pa, vh[2], vh[3]);
            }
        }
    }

    l0r += __shfl_xor_sync(0xffffffffu, l0r, 1);
    l0r += __shfl_xor_sync(0xffffffffu, l0r, 2);
    l1r += __shfl_xor_sync(0xffffffffu, l1r, 1);
    l1r += __shfl_xor_sync(0xffffffffu, l1r, 2);

    const float inv0 = 1.f / l0r;
    const float inv1 = 1.f / l1r;
    const size_t r0 = tokbase + q0 + warp * 16 + g;
    const size_t r1 = r0 + 8;
    const int cbase = h * 64 + 2 * tg;
#pragma unroll
    for (int nt = 0; nt < 8; nt++) {
        int c = cbase + nt * 8;
        __nv_bfloat162 h0 = __floats2bfloat162_rn(accO[nt][0] * inv0,
                                                  accO[nt][1] * inv0);
        __nv_bfloat162 h1 = __floats2bfloat162_rn(accO[nt][2] * inv1,
                                                  accO[nt][3] * inv1);
        *(__nv_bfloat162*)&o[r0 * D_ + c] = h0;
        *(__nv_bfloat162*)&o[r1 * D_ + c] = h1;
    }
}

// ---------------------------------------------------------------------------
// LayerNorm over last dim (D=1024), float4-vectorized.
// MODE 1: also emit tf32-rounded f32 copy.
// ---------------------------------------------------------------------------
template <int MODE>
__global__ __launch_bounds__(256)
void layernorm_kernel(const float* __restrict__ x, const float* __restrict__ gw,
                      const float* __restrict__ bw, float* __restrict__ out,
                      float* __restrict__ outT)
{
    __shared__ float rs[8], rs2[8];
    const int row = blockIdx.x;
    const int tid = threadIdx.x;

    float4 v = ((const float4*)(x + (size_t)row * D_))[tid];
    float s  = v.x + v.y + v.z + v.w;
    float s2 = v.x * v.x + v.y * v.y + v.z * v.z + v.w * v.w;
#pragma unroll
    for (int off = 16; off; off >>= 1) {
        s  += __shfl_xor_sync(0xffffffffu, s,  off);
        s2 += __shfl_xor_sync(0xffffffffu, s2, off);
    }
    if ((tid & 31) == 0) { rs[tid >> 5] = s; rs2[tid >> 5] = s2; }
    __syncthreads();
    float ts = 0.f, ts2 = 0.f;
#pragma unroll
    for (int i = 0; i < 8; i++) { ts += rs[i]; ts2 += rs2[i]; }

    const float mu  = ts * (1.0f / D_);
    const float var = ts2 * (1.0f / D_) - mu * mu;
    const float inv = rsqrtf(var + 1e-5f);

    float4 gg = ((const float4*)gw)[tid];
    float4 bb = ((const float4*)bw)[tid];
    float4 o;
    o.x = (v.x - mu) * inv * gg.x + bb.x;
    o.y = (v.y - mu) * inv * gg.y + bb.y;
    o.z = (v.z - mu) * inv * gg.z + bb.z;
    o.w = (v.w - mu) * inv * gg.w + bb.w;
    ((float4*)(out + (size_t)row * D_))[tid] = o;
    if (MODE) {
        float4 ot;
        ot.x = to_tf32(o.x); ot.y = to_tf32(o.y);
        ot.z = to_tf32(o.z); ot.w = to_tf32(o.w);
        ((float4*)(outT + (size_t)row * D_))[tid] = ot;
    }
}

// ---------------------------------------------------------------------------
// kernel_launch
// Inputs: x wq bq wk bk wv bv wo bo ln1_g ln1_b w1 b1 w2 b2 ln2_g ln2_b
// Launch order tuned so ncu (-s 5 -c 1) profiles flash_attn_mma:
//   0 tobf16(x), 1 pack_b, 2 pack_w, 3 tobf16(wo), 4 QKV, 5 attention.
// FFN transposes forked onto a side stream AFTER attention launch (overlap).
// ---------------------------------------------------------------------------
extern "C" void kernel_launch(void* const* d_in, const int* in_sizes, int n_in,
                              void* d_out, int out_size)
{
    (void)in_sizes; (void)n_in; (void)out_size;
    const float* x     = (const float*)d_in[0];
    const float* wq    = (const float*)d_in[1];
    const float* bq    = (const float*)d_in[2];
    const float* wk    = (const float*)d_in[3];
    const float* bk    = (const float*)d_in[4];
    const float* wv    = (const float*)d_in[5];
    const float* bv    = (const float*)d_in[6];
    const float* wo    = (const float*)d_in[7];
    const float* bo    = (const float*)d_in[8];
    const float* ln1g  = (const float*)d_in[9];
    const float* ln1b  = (const float*)d_in[10];
    const float* w1    = (const float*)d_in[11];
    const float* b1    = (const float*)d_in[12];
    const float* w2    = (const float*)d_in[13];
    const float* b2    = (const float*)d_in[14];
    const float* ln2g  = (const float*)d_in[15];
    const float* ln2b  = (const float*)d_in[16];
    float* out = (float*)d_out;

    float *tmp, *y, *ytf, *ff, *bqkv, *w1t, *w2t;
    __nv_bfloat16 *xh, *qkv, *attn, *wqkvh, *woh;
    cudaGetSymbolAddress((void**)&tmp,   g_tmp);
    cudaGetSymbolAddress((void**)&y,     g_y);
    cudaGetSymbolAddress((void**)&ytf,   g_ytf);
    cudaGetSymbolAddress((void**)&ff,    g_ff);
    cudaGetSymbolAddress((void**)&bqkv,  g_bqkv);
    cudaGetSymbolAddress((void**)&w1t,   g_w1t);
    cudaGetSymbolAddress((void**)&w2t,   g_w2t);
    cudaGetSymbolAddress((void**)&xh,    g_x_h);
    cudaGetSymbolAddress((void**)&qkv,   g_qkv);
    cudaGetSymbolAddress((void**)&attn,  g_attn);
    cudaGetSymbolAddress((void**)&wqkvh, g_wqkv_h);
    cudaGetSymbolAddress((void**)&woh,   g_wo_h);

    cudaFuncSetAttribute(mma_gemm_b16<1>,
        cudaFuncAttributeMaxDynamicSharedMemorySize, SMEM_1);
    cudaFuncSetAttribute(mma_gemm_b16<0>,
        cudaFuncAttributeMaxDynamicSharedMemorySize, SMEM_1);
    cudaFuncSetAttribute(tf32_gemm<1, 1>,
        cudaFuncAttributeMaxDynamicSharedMemorySize, SMEM_T);
    cudaFuncSetAttribute(tf32_gemm<0, 0>,
        cudaFuncAttributeMaxDynamicSharedMemorySize, SMEM_T);

    cudaStream_t s2;
    cudaStreamCreateWithFlags(&s2, cudaStreamNonBlocking);
    cudaEvent_t eFork, eJoin;
    cudaEventCreateWithFlags(&eFork, cudaEventDisableTiming);
    cudaEventCreateWithFlags(&eJoin, cudaEventDisableTiming);

    // Launches 0-3: all prep needed before attention-profiling point
    size_t nx4 = (size_t)NTOK * D_ / 4;
    tobf16_v4<<<(unsigned)((nx4 + 255) / 256), 256>>>(x, xh, nx4);         // 0
    pack_qkv_b<<<(NQKV + 255) / 256, 256>>>(bq, bk, bv, bqkv);             // 1
    size_t nq4 = (size_t)D_ * NQKV / 4;
    pack_qkv_w4<<<(unsigned)((nq4 + 255) / 256), 256>>>(wq, wk, wv, wqkvh); // 2
    size_t nwo4 = (size_t)D_ * D_ / 4;
    tobf16_v4<<<(unsigned)((nwo4 + 255) / 256), 256>>>(wo, woh, nwo4);     // 3

    // Launch 4: QKV projection (bf16) -> fused bf16 buffer
    mma_gemm_b16<1><<<dim3(NQKV / 128, NTOK / 128), 256, SMEM_1>>>(
        xh, wqkvh, bqkv, nullptr, nullptr, qkv, NTOK, NQKV, D_);

    // Launch 5: flash attention (ncu -s 5 -c 1 profiles this)
    {
        size_t smem = (size_t)(128 + 4 * 64) * QP * sizeof(__nv_bfloat16);
        cudaFuncSetAttribute(flash_attn_mma,
                             cudaFuncAttributeMaxDynamicSharedMemorySize, (int)smem);
        flash_attn_mma<<<dim3(S_ / 128, H_, B_), 256, smem>>>(qkv, attn);
    }

    // Fork AFTER attention launch: FFN weight transposes overlap attention
    cudaEventRecord(eFork, 0);
    cudaStreamWaitEvent(s2, eFork, 0);
    transpose_tf32<<<dim3(F_ / 32, D_ / 32), dim3(32, 8), 0, s2>>>(
        w1, w1t, D_, F_);
    transpose_tf32<<<dim3(D_ / 32, F_ / 32), dim3(32, 8), 0, s2>>>(
        w2, w2t, F_, D_);
    cudaEventRecord(eJoin, s2);

    // Output projection (bf16) + bias + residual(x) -> f32 tmp
    mma_gemm_b16<0><<<dim3(D_ / 128, NTOK / 128), 256, SMEM_1>>>(
        attn, woh, bo, x, tmp, nullptr, NTOK, D_, D_);

    // LayerNorm 1 -> y (exact f32) + ytf (tf32)
    layernorm_kernel<1><<<NTOK, 256>>>(tmp, ln1g, ln1b, y, ytf);

    // Join side stream before consuming w1t / w2t
    cudaStreamWaitEvent(0, eJoin, 0);

    // FFN up (tf32, occ2): relu(y @ w1 + b1) -> ff (tf32-rounded f32)
    tf32_gemm<1, 1><<<dim3(F_ / 128, NTOK / 128), 256, SMEM_T>>>(
        ytf, w1t, b1, nullptr, ff, NTOK, F_, D_);

    // FFN down (tf32, occ2) + bias + residual(y) -> f32 tmp
    tf32_gemm<0, 0><<<dim3(D_ / 128, NTOK / 128), 256, SMEM_T>>>(
        ff, w2t, b2, y, tmp, NTOK, D_, F_);

    // LayerNorm 2 -> output
    layernorm_kernel<0><<<NTOK, 256>>>(tmp, ln2g, ln2b, out, nullptr);
}